// round 15
// baseline (speedup 1.0000x reference)
#include <cuda_runtime.h>
#include <cuda_bf16.h>
#include <math.h>
#include <stdint.h>

#define BB 64
#define NN 512
#define DD 128
#define PITCH 136   // bf16 elems per smem row (272B): conflict-free ldmatrix
#define PITCH2 40   // bf16 elems per smem row for 32-wide k-chunks (80B)

typedef unsigned long long ull;

__device__ __forceinline__ unsigned sm32(const void* p){
    return (unsigned)__cvta_generic_to_shared(p);
}
__device__ __forceinline__ void cp16(unsigned dst, const void* src){
    asm volatile("cp.async.cg.shared.global [%0], [%1], 16;" :: "r"(dst), "l"(src));
}
__device__ __forceinline__ void cp_commit(){ asm volatile("cp.async.commit_group;"); }
__device__ __forceinline__ void cp_wait0(){ asm volatile("cp.async.wait_group 0;" ::: "memory"); }
__device__ __forceinline__ void cp_wait1(){ asm volatile("cp.async.wait_group 1;" ::: "memory"); }

// ---- warp-level MMA primitives ----
__device__ __forceinline__ void ldmA(uint32_t* a, uint32_t addr){
    asm volatile("ldmatrix.sync.aligned.m8n8.x4.shared.b16 {%0,%1,%2,%3}, [%4];"
        : "=r"(a[0]), "=r"(a[1]), "=r"(a[2]), "=r"(a[3]) : "r"(addr));
}
__device__ __forceinline__ void ldmB4(uint32_t* b, uint32_t addr){
    asm volatile("ldmatrix.sync.aligned.m8n8.x4.shared.b16 {%0,%1,%2,%3}, [%4];"
        : "=r"(b[0]), "=r"(b[1]), "=r"(b[2]), "=r"(b[3]) : "r"(addr));
}
__device__ __forceinline__ void mma16816(float* d, const uint32_t* a, const uint32_t* b){
    asm volatile("mma.sync.aligned.m16n8k16.row.col.f32.bf16.bf16.f32 "
        "{%0,%1,%2,%3}, {%4,%5,%6,%7}, {%8,%9}, {%0,%1,%2,%3};"
        : "+f"(d[0]), "+f"(d[1]), "+f"(d[2]), "+f"(d[3])
        : "r"(a[0]), "r"(a[1]), "r"(a[2]), "r"(a[3]), "r"(b[0]), "r"(b[1]));
}
__device__ __forceinline__ uint32_t packbf(float lo, float hi){
    __nv_bfloat162 v = __halves2bfloat162(__float2bfloat16(lo), __float2bfloat16(hi));
    return *(uint32_t*)&v;
}

// Scratch (static device globals; no allocation)
__device__ __nv_bfloat16 g_Ehi[(size_t)BB*NN*DD];
__device__ __nv_bfloat16 g_Elo[(size_t)BB*NN*DD];
__device__ __nv_bfloat16 g_Wthi[DD*DD];
__device__ __nv_bfloat16 g_Wtlo[DD*DD];
__device__ __nv_bfloat16 g_zThi[(size_t)BB*DD*NN];
__device__ __nv_bfloat16 g_zTlo[(size_t)BB*DD*NN];
__device__ float g_psum[BB*8*DD];
__device__ float g_eel [BB*NN];
__device__ float g_eel2[BB*NN];
__device__ float g_eer [BB*NN];
__device__ float g_eer2[BB*NN];
__device__ float g_th[BB];
__device__ float g_pool[BB*4*DD];

// ---------------- E -> bf16 hi/lo split + column partial sums ----------------
__global__ void k_split(const float* __restrict__ E){
    __shared__ float4 red[8][32];
    int b = blockIdx.y, rc = blockIdx.x;
    int tid = threadIdx.x;
    int r = tid >> 5, d4 = tid & 31;
    const float* Eb = E + (size_t)b*NN*DD + (size_t)rc*64*DD;
    __nv_bfloat16* Eh = g_Ehi + (size_t)b*NN*DD + (size_t)rc*64*DD;
    __nv_bfloat16* El = g_Elo + (size_t)b*NN*DD + (size_t)rc*64*DD;
    float4 ps = make_float4(0.f,0.f,0.f,0.f);
    #pragma unroll
    for (int q = 0; q < 8; q++){
        size_t off = (size_t)(r + q*8)*DD + d4*4;
        float4 v = *(const float4*)(Eb + off);
        __nv_bfloat16 h0 = __float2bfloat16(v.x), h1 = __float2bfloat16(v.y);
        __nv_bfloat16 h2 = __float2bfloat16(v.z), h3 = __float2bfloat16(v.w);
        *(__nv_bfloat162*)&Eh[off]   = __halves2bfloat162(h0, h1);
        *(__nv_bfloat162*)&Eh[off+2] = __halves2bfloat162(h2, h3);
        *(__nv_bfloat162*)&El[off]   = __halves2bfloat162(
            __float2bfloat16(v.x - __bfloat162float(h0)), __float2bfloat16(v.y - __bfloat162float(h1)));
        *(__nv_bfloat162*)&El[off+2] = __halves2bfloat162(
            __float2bfloat16(v.z - __bfloat162float(h2)), __float2bfloat16(v.w - __bfloat162float(h3)));
        ps.x += v.x; ps.y += v.y; ps.z += v.z; ps.w += v.w;
    }
    red[r][d4] = ps;
    __syncthreads();
    if (r == 0){
        float4 s = red[0][d4];
        #pragma unroll
        for (int q = 1; q < 8; q++){
            s.x += red[q][d4].x; s.y += red[q][d4].y;
            s.z += red[q][d4].z; s.w += red[q][d4].w;
        }
        *(float4*)&g_psum[(b*8 + rc)*DD + d4*4] = s;
    }
}

// ---------------- W -> W^T bf16 hi/lo ----------------
__global__ void k_Wt(const float* __restrict__ W){
    __shared__ float t[32][33];
    int k0 = blockIdx.x * 32;
    int d0 = blockIdx.y * 32;
    int tx = threadIdx.x, ty = threadIdx.y;
    #pragma unroll
    for (int yy = 0; yy < 32; yy += 8)
        t[ty+yy][tx] = W[(size_t)(k0+ty+yy)*DD + d0 + tx];
    __syncthreads();
    #pragma unroll
    for (int yy = 0; yy < 32; yy += 8){
        float v = t[tx][ty+yy];
        size_t idx = (size_t)(d0+ty+yy)*DD + k0 + tx;
        __nv_bfloat16 h = __float2bfloat16(v);
        g_Wthi[idx] = h;
        g_Wtlo[idx] = __float2bfloat16(v - __bfloat162float(h));
    }
}

// ---------------- thresh from partial sums ----------------
__global__ void k_thresh(){
    int b = blockIdx.x; int t = threadIdx.x;
    float s = 0.f;
    #pragma unroll
    for (int q = 0; q < 8; q++) s += g_psum[(b*8 + q)*DD + t];
    __shared__ float red[DD];
    red[t] = s * s;
    __syncthreads();
    for (int o = 64; o > 0; o >>= 1){
        if (t < o) red[t] += red[t+o];
        __syncthreads();
    }
    if (t == 0) g_th[b] = red[0] * (1.f / ((float)NN * (float)NN));
}

#define TILEB1 (128*PITCH*2)            // 34816

#define LDTILE(dstoff, Src) do { \
    _Pragma("unroll") \
    for (int _p = 0; _p < 8; _p++){ \
        int _cid = tid + 256*_p; \
        int _row = _cid >> 4, _kc = _cid & 15; \
        cp16(sb + (dstoff) + (_row*PITCH + _kc*8)*2, (Src) + (size_t)_row*DD + _kc*8); \
    } \
} while(0)

// ---------------- HMMA z^T: merged terms, x4 B-loads ----------------
#define SMS_T0 0
#define SMS_T1 TILEB1
#define SMS_T2 (2*TILEB1)
#define SMZ_RED (3*TILEB1)
#define SMEM_Z  (SMZ_RED + 4096)

__global__ void __launch_bounds__(256,2) k_z_mma(const float* __restrict__ attn_l,
                                                 const float* __restrict__ attn_r){
    extern __shared__ char smem[];
    uint32_t sb = sm32(smem);
    float* rel = (float*)(smem + SMZ_RED);
    float* rer = rel + 256;

    int tid = threadIdx.x;
    int wid = tid >> 5, lane = tid & 31;
    int warp_m = wid >> 2, warp_n = wid & 3;
    int g = lane >> 2, t = lane & 3;
    int it = blockIdx.x, b = blockIdx.y;
    int i0 = it * 128;

    uint32_t aoff[4];
    #pragma unroll
    for (int mt = 0; mt < 4; mt++)
        aoff[mt] = ((warp_m*64 + mt*16 + (lane & 15))*PITCH + (lane >> 4)*8)*2;
    // x4 B: lanes 0-15 -> first n8 group, 16-31 -> second
    uint32_t boff4 = ((warp_n*32 + (lane & 7) + ((lane >> 4) << 3))*PITCH + ((lane >> 3) & 1)*8)*2;

    float d[4][4][4];
    #pragma unroll
    for (int mt = 0; mt < 4; mt++)
        #pragma unroll
        for (int nt = 0; nt < 4; nt++)
            #pragma unroll
            for (int c = 0; c < 4; c++) d[mt][nt][c] = 0.f;

    const __nv_bfloat16* Eh = g_Ehi + (size_t)b*NN*DD + (size_t)i0*DD;
    const __nv_bfloat16* El = g_Elo + (size_t)b*NN*DD + (size_t)i0*DD;

    float al8[8], ar8[8];
    #pragma unroll
    for (int mt = 0; mt < 4; mt++)
        #pragma unroll
        for (int half = 0; half < 2; half++){
            int dloc = warp_m*64 + mt*16 + g + 8*half;
            al8[mt*2+half] = attn_l[dloc];
            ar8[mt*2+half] = attn_r[dloc];
        }

    LDTILE(SMS_T0, g_Wthi);
    LDTILE(SMS_T1, El);
    cp_commit();
    LDTILE(SMS_T2, Eh);
    cp_commit();

    cp_wait1();
    __syncthreads();
    // term0: Wth x El (x4 B)
    #pragma unroll 2
    for (int ks = 0; ks < 8; ks++){
        uint32_t af[4][4], b0[4], b1[4];
        #pragma unroll
        for (int mt = 0; mt < 4; mt++) ldmA(af[mt], sb + SMS_T0 + aoff[mt] + ks*32);
        ldmB4(b0, sb + SMS_T1 + boff4 + ks*32);
        ldmB4(b1, sb + SMS_T1 + boff4 + 16*PITCH*2 + ks*32);
        #pragma unroll
        for (int mt = 0; mt < 4; mt++){
            mma16816(d[mt][0], af[mt], &b0[0]); mma16816(d[mt][1], af[mt], &b0[2]);
            mma16816(d[mt][2], af[mt], &b1[0]); mma16816(d[mt][3], af[mt], &b1[2]);
        }
    }
    __syncthreads();
    LDTILE(SMS_T1, g_Wtlo);
    cp_commit();
    cp_wait0();
    __syncthreads();
    // merged terms 1+2: (Wth, Wtl) x Eh — B loaded once
    #pragma unroll 2
    for (int ks = 0; ks < 8; ks++){
        uint32_t ah[4][4], al_[4][4], b0[4], b1[4];
        #pragma unroll
        for (int mt = 0; mt < 4; mt++) ldmA(ah[mt],  sb + SMS_T0 + aoff[mt] + ks*32);
        #pragma unroll
        for (int mt = 0; mt < 4; mt++) ldmA(al_[mt], sb + SMS_T1 + aoff[mt] + ks*32);
        ldmB4(b0, sb + SMS_T2 + boff4 + ks*32);
        ldmB4(b1, sb + SMS_T2 + boff4 + 16*PITCH*2 + ks*32);
        #pragma unroll
        for (int mt = 0; mt < 4; mt++){
            mma16816(d[mt][0], ah[mt], &b0[0]); mma16816(d[mt][1], ah[mt], &b0[2]);
            mma16816(d[mt][2], ah[mt], &b1[0]); mma16816(d[mt][3], ah[mt], &b1[2]);
        }
        #pragma unroll
        for (int mt = 0; mt < 4; mt++){
            mma16816(d[mt][0], al_[mt], &b0[0]); mma16816(d[mt][1], al_[mt], &b0[2]);
            mma16816(d[mt][2], al_[mt], &b1[0]); mma16816(d[mt][3], al_[mt], &b1[2]);
        }
    }

    __nv_bfloat16* zh = g_zThi + (size_t)b*DD*NN;
    __nv_bfloat16* zl = g_zTlo + (size_t)b*DD*NN;
    float pel[8], per_[8];
    #pragma unroll
    for (int q = 0; q < 8; q++){ pel[q] = 0.f; per_[q] = 0.f; }
    #pragma unroll
    for (int mt = 0; mt < 4; mt++){
        #pragma unroll
        for (int half = 0; half < 2; half++){
            int dloc = warp_m*64 + mt*16 + g + 8*half;
            float wl = al8[mt*2+half], wr = ar8[mt*2+half];
            #pragma unroll
            for (int nt = 0; nt < 4; nt++){
                float v0 = d[mt][nt][half*2 + 0];
                float v1 = d[mt][nt][half*2 + 1];
                pel[nt*2+0] += wl*v0; pel[nt*2+1] += wl*v1;
                per_[nt*2+0] += wr*v0; per_[nt*2+1] += wr*v1;
                __nv_bfloat16 h0 = __float2bfloat16(v0);
                __nv_bfloat16 h1 = __float2bfloat16(v1);
                __nv_bfloat16 l0 = __float2bfloat16(v0 - __bfloat162float(h0));
                __nv_bfloat16 l1 = __float2bfloat16(v1 - __bfloat162float(h1));
                size_t addr = (size_t)dloc*NN + i0 + warp_n*32 + nt*8 + 2*t;
                *(__nv_bfloat162*)&zh[addr] = __halves2bfloat162(h0, h1);
                *(__nv_bfloat162*)&zl[addr] = __halves2bfloat162(l0, l1);
            }
        }
    }
    #pragma unroll
    for (int q = 0; q < 8; q++){
        pel[q] += __shfl_xor_sync(0xFFFFFFFFu, pel[q], 4);
        pel[q] += __shfl_xor_sync(0xFFFFFFFFu, pel[q], 8);
        pel[q] += __shfl_xor_sync(0xFFFFFFFFu, pel[q], 16);
        per_[q] += __shfl_xor_sync(0xFFFFFFFFu, per_[q], 4);
        per_[q] += __shfl_xor_sync(0xFFFFFFFFu, per_[q], 8);
        per_[q] += __shfl_xor_sync(0xFFFFFFFFu, per_[q], 16);
    }
    __syncthreads();
    if (g == 0){
        #pragma unroll
        for (int nt = 0; nt < 4; nt++)
            #pragma unroll
            for (int par = 0; par < 2; par++){
                int iloc = warp_n*32 + nt*8 + 2*t + par;
                rel[warp_m*128 + iloc] = pel[nt*2+par];
                rer[warp_m*128 + iloc] = per_[nt*2+par];
            }
    }
    __syncthreads();
    if (tid < 128){
        float se = rel[tid] + rel[128 + tid];
        float sr = rer[tid] + rer[128 + tid];
        int gi = b*NN + i0 + tid;
        g_eel [gi] = __expf(se);
        g_eel2[gi] = __expf(0.2f*se);
        g_eer [gi] = __expf(sr);
        g_eer2[gi] = __expf(0.2f*sr);
    }
}

// ---------------- FUSED scores+PV (split accumulators, paired PV) ----------------
#define SPV_JH  0
#define SPV_JL  TILEB1
#define SPV_EIH (2*TILEB1)
#define SPV_EIL (SPV_EIH + 8704)
#define SPV_ZH  (SPV_EIL + 8704)
#define SPV_ZL  (SPV_ZH + 10240)
#define SPV_ELI (SPV_ZL + 10240)
#define SPV_ELI2 (SPV_ELI + 2048)
#define SPV_RED SPV_EIH
#define SMEM_SPV (SPV_ELI2 + 2048)

__global__ void __launch_bounds__(256,2) k_spv(const float* __restrict__ bias){
    extern __shared__ char smem[];
    uint32_t sb = sm32(smem);
    float* sEli  = (float*)(smem + SPV_ELI);
    float* sEli2 = (float*)(smem + SPV_ELI2);
    float* red   = (float*)(smem + SPV_RED);

    int tid = threadIdx.x;
    int w = tid >> 5, lane = tid & 31;
    int g = lane >> 2, t = lane & 3;
    int jt = blockIdx.x, b = blockIdx.y;
    int j0 = jt * 128;

    #pragma unroll
    for (int p = 0; p < 2; p++){
        sEli [tid + 256*p] = g_eel [b*NN + tid + 256*p];
        sEli2[tid + 256*p] = g_eel2[b*NN + tid + 256*p];
    }

    int jg0 = j0 + w*16 + g;
    float Er0  = g_eer [b*NN + jg0],     Er1  = g_eer [b*NN + jg0 + 8];
    float Er20 = g_eer2[b*NN + jg0],     Er21 = g_eer2[b*NN + jg0 + 8];
    float th = g_th[b];

    uint32_t aoffJ  = ((w*16 + (lane & 15))*PITCH + (lane >> 4)*8)*2;
    uint32_t boffE4 = (((lane & 7) + ((lane >> 4) << 3))*PITCH  + ((lane >> 3) & 1)*8)*2;
    uint32_t boffZ4 = (((lane & 7) + ((lane >> 4) << 3))*PITCH2 + ((lane >> 3) & 1)*8)*2;

    const __nv_bfloat16* Ehb = g_Ehi + (size_t)b*NN*DD;
    const __nv_bfloat16* Elb = g_Elo + (size_t)b*NN*DD;
    const __nv_bfloat16* zh  = g_zThi + (size_t)b*DD*NN;
    const __nv_bfloat16* zl  = g_zTlo + (size_t)b*DD*NN;

    LDTILE(SPV_JH, Ehb + (size_t)j0*DD);
    LDTILE(SPV_JL, Elb + (size_t)j0*DD);

    #define ISSUE_CHUNK(icv) do { \
        const __nv_bfloat16* _eh = Ehb + (size_t)((icv)*32)*DD; \
        const __nv_bfloat16* _el = Elb + (size_t)((icv)*32)*DD; \
        _Pragma("unroll") \
        for (int _p = 0; _p < 2; _p++){ \
            int _cid = tid + 256*_p; \
            int _row = _cid >> 4, _kc = _cid & 15; \
            cp16(sb + SPV_EIH + (_row*PITCH + _kc*8)*2, _eh + (size_t)_row*DD + _kc*8); \
            cp16(sb + SPV_EIL + (_row*PITCH + _kc*8)*2, _el + (size_t)_row*DD + _kc*8); \
        } \
        _Pragma("unroll") \
        for (int _p = 0; _p < 2; _p++){ \
            int _cid = tid + 256*_p; \
            int _row = _cid >> 2, _seg = _cid & 3; \
            cp16(sb + SPV_ZH + (_row*PITCH2 + _seg*8)*2, zh + (size_t)_row*NN + (icv)*32 + _seg*8); \
            cp16(sb + SPV_ZL + (_row*PITCH2 + _seg*8)*2, zl + (size_t)_row*NN + (icv)*32 + _seg*8); \
        } \
        cp_commit(); \
    } while(0)

    ISSUE_CHUNK(0);

    float hacc[16][4];
    #pragma unroll
    for (int q = 0; q < 16; q++)
        #pragma unroll
        for (int c = 0; c < 4; c++) hacc[q][c] = 0.f;
    float cs0 = 0.f, cs1 = 0.f;

    #pragma unroll 1
    for (int ic = 0; ic < 16; ic++){
        cp_wait0();
        __syncthreads();

        // ---- S accumulated in two banks to break RAW chains
        float s[4][4], s2[4][4];
        #pragma unroll
        for (int nt = 0; nt < 4; nt++)
            #pragma unroll
            for (int c = 0; c < 4; c++){ s[nt][c] = 0.f; s2[nt][c] = 0.f; }

        #pragma unroll 2
        for (int ks = 0; ks < 8; ks++){
            uint32_t aH[4], aL[4];
            ldmA(aH, sb + SPV_JH + aoffJ + ks*32);
            ldmA(aL, sb + SPV_JL + aoffJ + ks*32);
            uint32_t bH0[4], bH1[4], bL0[4], bL1[4];
            ldmB4(bH0, sb + SPV_EIH + boffE4 + ks*32);
            ldmB4(bH1, sb + SPV_EIH + boffE4 + 16*PITCH*2 + ks*32);
            ldmB4(bL0, sb + SPV_EIL + boffE4 + ks*32);
            ldmB4(bL1, sb + SPV_EIL + boffE4 + 16*PITCH*2 + ks*32);
            mma16816(s[0],  aH, &bH0[0]); mma16816(s[1],  aH, &bH0[2]);
            mma16816(s[2],  aH, &bH1[0]); mma16816(s[3],  aH, &bH1[2]);
            mma16816(s2[0], aH, &bL0[0]); mma16816(s2[1], aH, &bL0[2]);
            mma16816(s2[2], aH, &bL1[0]); mma16816(s2[3], aH, &bL1[2]);
            mma16816(s[0],  aL, &bH0[0]); mma16816(s[1],  aL, &bH0[2]);
            mma16816(s[2],  aL, &bH1[0]); mma16816(s[3],  aL, &bH1[2]);
        }

        // ---- mask/exp -> P in regs; cs accumulate
        int ibase = ic*32;
        #pragma unroll
        for (int nt = 0; nt < 4; nt++){
            #pragma unroll
            for (int c = 0; c < 4; c++){
                int ig = ibase + nt*8 + 2*t + (c & 1);
                int jg = jg0 + 8*(c >> 1);
                float sv = s[nt][c] + s2[nt][c];
                float p = 0.f;
                if (sv > th || ig == jg){
                    float q = sEli[ig] * ((c >> 1) ? Er1 : Er0);
                    p = (q > 1.f) ? q : sEli2[ig] * ((c >> 1) ? Er21 : Er20);
                }
                if (c >> 1) cs1 += p; else cs0 += p;
                s[nt][c] = p;
            }
        }

        // ---- C-frag -> A-frag
        uint32_t pf[2][4];
        #pragma unroll
        for (int kt = 0; kt < 2; kt++){
            pf[kt][0] = packbf(s[2*kt][0],   s[2*kt][1]);
            pf[kt][1] = packbf(s[2*kt][2],   s[2*kt][3]);
            pf[kt][2] = packbf(s[2*kt+1][0], s[2*kt+1][1]);
            pf[kt][3] = packbf(s[2*kt+1][2], s[2*kt+1][3]);
        }

        // ---- PV: paired ntp so each hacc repeats at distance 4
        #pragma unroll
        for (int kt = 0; kt < 2; kt++){
            #pragma unroll
            for (int np2 = 0; np2 < 4; np2++){
                uint32_t bhA[4], blA[4], bhB[4], blB[4];
                ldmB4(bhA, sb + SPV_ZH + boffZ4 + (2*np2)  *(16*PITCH2*2) + kt*32);
                ldmB4(blA, sb + SPV_ZL + boffZ4 + (2*np2)  *(16*PITCH2*2) + kt*32);
                ldmB4(bhB, sb + SPV_ZH + boffZ4 + (2*np2+1)*(16*PITCH2*2) + kt*32);
                ldmB4(blB, sb + SPV_ZL + boffZ4 + (2*np2+1)*(16*PITCH2*2) + kt*32);
                mma16816(hacc[4*np2+0], pf[kt], &bhA[0]);
                mma16816(hacc[4*np2+1], pf[kt], &bhA[2]);
                mma16816(hacc[4*np2+2], pf[kt], &bhB[0]);
                mma16816(hacc[4*np2+3], pf[kt], &bhB[2]);
                mma16816(hacc[4*np2+0], pf[kt], &blA[0]);
                mma16816(hacc[4*np2+1], pf[kt], &blA[2]);
                mma16816(hacc[4*np2+2], pf[kt], &blB[0]);
                mma16816(hacc[4*np2+3], pf[kt], &blB[2]);
            }
        }

        __syncthreads();
        if (ic + 1 < 16) ISSUE_CHUNK(ic+1);
    }
    #undef ISSUE_CHUNK

    // ---- final: cs reduce, /cs, +bias, elu, pool over j
    cs0 += __shfl_xor_sync(0xFFFFFFFFu, cs0, 1);
    cs0 += __shfl_xor_sync(0xFFFFFFFFu, cs0, 2);
    cs1 += __shfl_xor_sync(0xFFFFFFFFu, cs1, 1);
    cs1 += __shfl_xor_sync(0xFFFFFFFFu, cs1, 2);
    float inv0 = 1.f / cs0, inv1 = 1.f / cs1;

    #pragma unroll
    for (int ntd = 0; ntd < 16; ntd++){
        float pd0, pd1;
        {
            float v0 = hacc[ntd][0]*inv0 + bias[ntd*8 + 2*t];
            float v1 = hacc[ntd][1]*inv0 + bias[ntd*8 + 2*t + 1];
            float v2 = hacc[ntd][2]*inv1 + bias[ntd*8 + 2*t];
            float v3 = hacc[ntd][3]*inv1 + bias[ntd*8 + 2*t + 1];
            v0 = v0 > 0.f ? v0 : expm1f(v0);
            v1 = v1 > 0.f ? v1 : expm1f(v1);
            v2 = v2 > 0.f ? v2 : expm1f(v2);
            v3 = v3 > 0.f ? v3 : expm1f(v3);
            pd0 = v0 + v2; pd1 = v1 + v3;
        }
        pd0 += __shfl_xor_sync(0xFFFFFFFFu, pd0, 4);
        pd0 += __shfl_xor_sync(0xFFFFFFFFu, pd0, 8);
        pd0 += __shfl_xor_sync(0xFFFFFFFFu, pd0, 16);
        pd1 += __shfl_xor_sync(0xFFFFFFFFu, pd1, 4);
        pd1 += __shfl_xor_sync(0xFFFFFFFFu, pd1, 8);
        pd1 += __shfl_xor_sync(0xFFFFFFFFu, pd1, 16);
        if (g == 0){
            red[w*128 + ntd*8 + 2*t]     = pd0;
            red[w*128 + ntd*8 + 2*t + 1] = pd1;
        }
    }
    __syncthreads();
    if (tid < 128){
        float tt = 0.f;
        #pragma unroll
        for (int x = 0; x < 8; x++) tt += red[x*128 + tid];
        g_pool[(b*4 + jt)*DD + tid] = tt;
    }
}

// ---------------- final: mean over nodes ----------------
__global__ void k_out(float* __restrict__ out){
    int b = blockIdx.x, d = threadIdx.x;
    float s = g_pool[(b*4+0)*DD + d] + g_pool[(b*4+1)*DD + d]
            + g_pool[(b*4+2)*DD + d] + g_pool[(b*4+3)*DD + d];
    out[b*DD + d] = s * (1.f / (float)NN);
}

extern "C" void kernel_launch(void* const* d_in, const int* in_sizes, int n_in,
                              void* d_out, int out_size){
    const float* E    = (const float*)d_in[0];
    const float* W    = (const float*)d_in[1];
    const float* al   = (const float*)d_in[2];
    const float* ar   = (const float*)d_in[3];
    const float* bias = (const float*)d_in[4];
    float* out = (float*)d_out;

    cudaFuncSetAttribute(k_z_mma, cudaFuncAttributeMaxDynamicSharedMemorySize, SMEM_Z);
    cudaFuncSetAttribute(k_spv,   cudaFuncAttributeMaxDynamicSharedMemorySize, SMEM_SPV);

    k_split <<<dim3(8,64), 256>>>(E);
    k_Wt    <<<dim3(4,4), dim3(32,8)>>>(W);
    k_thresh<<<64, 128>>>();
    k_z_mma <<<dim3(4,64), 256, SMEM_Z>>>(al, ar);
    k_spv   <<<dim3(4,64), 256, SMEM_SPV>>>(bias);
    k_out   <<<64, 128>>>(out);
}

// round 16
// speedup vs baseline: 1.0038x; 1.0038x over previous
#include <cuda_runtime.h>
#include <cuda_bf16.h>
#include <math.h>
#include <stdint.h>

#define BB 64
#define NN 512
#define DD 128
#define PITCH 136   // bf16 elems per smem row (272B): conflict-free ldmatrix
#define PITCH2 40   // bf16 elems per smem row for 32-wide k-chunks (80B)

typedef unsigned long long ull;

__device__ __forceinline__ unsigned sm32(const void* p){
    return (unsigned)__cvta_generic_to_shared(p);
}
__device__ __forceinline__ void cp16(unsigned dst, const void* src){
    asm volatile("cp.async.cg.shared.global [%0], [%1], 16;" :: "r"(dst), "l"(src));
}
__device__ __forceinline__ void cp_commit(){ asm volatile("cp.async.commit_group;"); }
__device__ __forceinline__ void cp_wait0(){ asm volatile("cp.async.wait_group 0;" ::: "memory"); }
__device__ __forceinline__ void cp_wait1(){ asm volatile("cp.async.wait_group 1;" ::: "memory"); }

// ---- warp-level MMA primitives ----
__device__ __forceinline__ void ldmA(uint32_t* a, uint32_t addr){
    asm volatile("ldmatrix.sync.aligned.m8n8.x4.shared.b16 {%0,%1,%2,%3}, [%4];"
        : "=r"(a[0]), "=r"(a[1]), "=r"(a[2]), "=r"(a[3]) : "r"(addr));
}
__device__ __forceinline__ void ldmB4(uint32_t* b, uint32_t addr){
    asm volatile("ldmatrix.sync.aligned.m8n8.x4.shared.b16 {%0,%1,%2,%3}, [%4];"
        : "=r"(b[0]), "=r"(b[1]), "=r"(b[2]), "=r"(b[3]) : "r"(addr));
}
__device__ __forceinline__ void ldmB(uint32_t* b, uint32_t addr){
    asm volatile("ldmatrix.sync.aligned.m8n8.x2.shared.b16 {%0,%1}, [%2];"
        : "=r"(b[0]), "=r"(b[1]) : "r"(addr));
}
// NOTE: non-volatile — pure register dataflow, lets ptxas schedule freely.
__device__ __forceinline__ void mma16816(float* d, const uint32_t* a, const uint32_t* b){
    asm("mma.sync.aligned.m16n8k16.row.col.f32.bf16.bf16.f32 "
        "{%0,%1,%2,%3}, {%4,%5,%6,%7}, {%8,%9}, {%0,%1,%2,%3};"
        : "+f"(d[0]), "+f"(d[1]), "+f"(d[2]), "+f"(d[3])
        : "r"(a[0]), "r"(a[1]), "r"(a[2]), "r"(a[3]), "r"(b[0]), "r"(b[1]));
}
__device__ __forceinline__ uint32_t packbf(float lo, float hi){
    __nv_bfloat162 v = __halves2bfloat162(__float2bfloat16(lo), __float2bfloat16(hi));
    return *(uint32_t*)&v;
}

// Scratch (static device globals; no allocation)
__device__ __nv_bfloat16 g_Ehi[(size_t)BB*NN*DD];
__device__ __nv_bfloat16 g_Elo[(size_t)BB*NN*DD];
__device__ __nv_bfloat16 g_Wthi[DD*DD];
__device__ __nv_bfloat16 g_Wtlo[DD*DD];
__device__ __nv_bfloat16 g_zThi[(size_t)BB*DD*NN];
__device__ __nv_bfloat16 g_zTlo[(size_t)BB*DD*NN];
__device__ float g_psum[BB*8*DD];
__device__ float g_eel [BB*NN];
__device__ float g_eel2[BB*NN];
__device__ float g_eer [BB*NN];
__device__ float g_eer2[BB*NN];
__device__ float g_th[BB];
__device__ float g_pool[BB*4*DD];

// ---------------- E -> bf16 hi/lo split + column partial sums ----------------
__global__ void k_split(const float* __restrict__ E){
    __shared__ float4 red[8][32];
    int b = blockIdx.y, rc = blockIdx.x;
    int tid = threadIdx.x;
    int r = tid >> 5, d4 = tid & 31;
    const float* Eb = E + (size_t)b*NN*DD + (size_t)rc*64*DD;
    __nv_bfloat16* Eh = g_Ehi + (size_t)b*NN*DD + (size_t)rc*64*DD;
    __nv_bfloat16* El = g_Elo + (size_t)b*NN*DD + (size_t)rc*64*DD;
    float4 ps = make_float4(0.f,0.f,0.f,0.f);
    #pragma unroll
    for (int q = 0; q < 8; q++){
        size_t off = (size_t)(r + q*8)*DD + d4*4;
        float4 v = *(const float4*)(Eb + off);
        __nv_bfloat16 h0 = __float2bfloat16(v.x), h1 = __float2bfloat16(v.y);
        __nv_bfloat16 h2 = __float2bfloat16(v.z), h3 = __float2bfloat16(v.w);
        *(__nv_bfloat162*)&Eh[off]   = __halves2bfloat162(h0, h1);
        *(__nv_bfloat162*)&Eh[off+2] = __halves2bfloat162(h2, h3);
        *(__nv_bfloat162*)&El[off]   = __halves2bfloat162(
            __float2bfloat16(v.x - __bfloat162float(h0)), __float2bfloat16(v.y - __bfloat162float(h1)));
        *(__nv_bfloat162*)&El[off+2] = __halves2bfloat162(
            __float2bfloat16(v.z - __bfloat162float(h2)), __float2bfloat16(v.w - __bfloat162float(h3)));
        ps.x += v.x; ps.y += v.y; ps.z += v.z; ps.w += v.w;
    }
    red[r][d4] = ps;
    __syncthreads();
    if (r == 0){
        float4 s = red[0][d4];
        #pragma unroll
        for (int q = 1; q < 8; q++){
            s.x += red[q][d4].x; s.y += red[q][d4].y;
            s.z += red[q][d4].z; s.w += red[q][d4].w;
        }
        *(float4*)&g_psum[(b*8 + rc)*DD + d4*4] = s;
    }
}

// ---------------- W -> W^T bf16 hi/lo ----------------
__global__ void k_Wt(const float* __restrict__ W){
    __shared__ float t[32][33];
    int k0 = blockIdx.x * 32;
    int d0 = blockIdx.y * 32;
    int tx = threadIdx.x, ty = threadIdx.y;
    #pragma unroll
    for (int yy = 0; yy < 32; yy += 8)
        t[ty+yy][tx] = W[(size_t)(k0+ty+yy)*DD + d0 + tx];
    __syncthreads();
    #pragma unroll
    for (int yy = 0; yy < 32; yy += 8){
        float v = t[tx][ty+yy];
        size_t idx = (size_t)(d0+ty+yy)*DD + k0 + tx;
        __nv_bfloat16 h = __float2bfloat16(v);
        g_Wthi[idx] = h;
        g_Wtlo[idx] = __float2bfloat16(v - __bfloat162float(h));
    }
}

// ---------------- thresh from partial sums ----------------
__global__ void k_thresh(){
    int b = blockIdx.x; int t = threadIdx.x;
    float s = 0.f;
    #pragma unroll
    for (int q = 0; q < 8; q++) s += g_psum[(b*8 + q)*DD + t];
    __shared__ float red[DD];
    red[t] = s * s;
    __syncthreads();
    for (int o = 64; o > 0; o >>= 1){
        if (t < o) red[t] += red[t+o];
        __syncthreads();
    }
    if (t == 0) g_th[b] = red[0] * (1.f / ((float)NN * (float)NN));
}

#define TILEB1 (128*PITCH*2)            // 34816

#define LDTILE(dstoff, Src) do { \
    _Pragma("unroll") \
    for (int _p = 0; _p < 8; _p++){ \
        int _cid = tid + 256*_p; \
        int _row = _cid >> 4, _kc = _cid & 15; \
        cp16(sb + (dstoff) + (_row*PITCH + _kc*8)*2, (Src) + (size_t)_row*DD + _kc*8); \
    } \
} while(0)

#define TERM(at, bt) do { \
    _Pragma("unroll 2") \
    for (int ks = 0; ks < 8; ks++){ \
        uint32_t af[4][4], bf[4][2]; \
        _Pragma("unroll") \
        for (int mt = 0; mt < 4; mt++) ldmA(af[mt], sb + (at) + aoff[mt] + ks*32); \
        _Pragma("unroll") \
        for (int nt = 0; nt < 4; nt++) ldmB(bf[nt], sb + (bt) + boff[nt] + ks*32); \
        _Pragma("unroll") \
        for (int mt = 0; mt < 4; mt++) \
            _Pragma("unroll") \
            for (int nt = 0; nt < 4; nt++) \
                mma16816(d[mt][nt], af[mt], bf[nt]); \
    } \
} while(0)

// ---------------- HMMA z^T (R14 version) ----------------
#define SMS_T0 0
#define SMS_T1 TILEB1
#define SMS_T2 (2*TILEB1)
#define SMZ_RED (3*TILEB1)
#define SMEM_Z  (SMZ_RED + 4096)

__global__ void __launch_bounds__(256,2) k_z_mma(const float* __restrict__ attn_l,
                                                 const float* __restrict__ attn_r){
    extern __shared__ char smem[];
    uint32_t sb = sm32(smem);
    float* rel = (float*)(smem + SMZ_RED);
    float* rer = rel + 256;

    int tid = threadIdx.x;
    int wid = tid >> 5, lane = tid & 31;
    int warp_m = wid >> 2, warp_n = wid & 3;
    int g = lane >> 2, t = lane & 3;
    int it = blockIdx.x, b = blockIdx.y;
    int i0 = it * 128;

    uint32_t aoff[4], boff[4];
    #pragma unroll
    for (int mt = 0; mt < 4; mt++)
        aoff[mt] = ((warp_m*64 + mt*16 + (lane & 15))*PITCH + (lane >> 4)*8)*2;
    #pragma unroll
    for (int nt = 0; nt < 4; nt++)
        boff[nt] = ((warp_n*32 + nt*8 + (lane & 7))*PITCH + ((lane >> 3) & 1)*8)*2;

    float d[4][4][4];
    #pragma unroll
    for (int mt = 0; mt < 4; mt++)
        #pragma unroll
        for (int nt = 0; nt < 4; nt++)
            #pragma unroll
            for (int c = 0; c < 4; c++) d[mt][nt][c] = 0.f;

    const __nv_bfloat16* Eh = g_Ehi + (size_t)b*NN*DD + (size_t)i0*DD;
    const __nv_bfloat16* El = g_Elo + (size_t)b*NN*DD + (size_t)i0*DD;

    float al8[8], ar8[8];
    #pragma unroll
    for (int mt = 0; mt < 4; mt++)
        #pragma unroll
        for (int half = 0; half < 2; half++){
            int dloc = warp_m*64 + mt*16 + g + 8*half;
            al8[mt*2+half] = attn_l[dloc];
            ar8[mt*2+half] = attn_r[dloc];
        }

    LDTILE(SMS_T0, g_Wthi);
    LDTILE(SMS_T1, El);
    cp_commit();
    LDTILE(SMS_T2, Eh);
    cp_commit();

    cp_wait1();
    __syncthreads();
    TERM(SMS_T0, SMS_T1);
    __syncthreads();
    LDTILE(SMS_T1, g_Wtlo);
    cp_commit();
    cp_wait1();
    __syncthreads();
    TERM(SMS_T0, SMS_T2);
    cp_wait0();
    __syncthreads();
    TERM(SMS_T1, SMS_T2);

    __nv_bfloat16* zh = g_zThi + (size_t)b*DD*NN;
    __nv_bfloat16* zl = g_zTlo + (size_t)b*DD*NN;
    float pel[8], per_[8];
    #pragma unroll
    for (int q = 0; q < 8; q++){ pel[q] = 0.f; per_[q] = 0.f; }
    #pragma unroll
    for (int mt = 0; mt < 4; mt++){
        #pragma unroll
        for (int half = 0; half < 2; half++){
            int dloc = warp_m*64 + mt*16 + g + 8*half;
            float wl = al8[mt*2+half], wr = ar8[mt*2+half];
            #pragma unroll
            for (int nt = 0; nt < 4; nt++){
                float v0 = d[mt][nt][half*2 + 0];
                float v1 = d[mt][nt][half*2 + 1];
                pel[nt*2+0] += wl*v0; pel[nt*2+1] += wl*v1;
                per_[nt*2+0] += wr*v0; per_[nt*2+1] += wr*v1;
                __nv_bfloat16 h0 = __float2bfloat16(v0);
                __nv_bfloat16 h1 = __float2bfloat16(v1);
                __nv_bfloat16 l0 = __float2bfloat16(v0 - __bfloat162float(h0));
                __nv_bfloat16 l1 = __float2bfloat16(v1 - __bfloat162float(h1));
                size_t addr = (size_t)dloc*NN + i0 + warp_n*32 + nt*8 + 2*t;
                *(__nv_bfloat162*)&zh[addr] = __halves2bfloat162(h0, h1);
                *(__nv_bfloat162*)&zl[addr] = __halves2bfloat162(l0, l1);
            }
        }
    }
    #pragma unroll
    for (int q = 0; q < 8; q++){
        pel[q] += __shfl_xor_sync(0xFFFFFFFFu, pel[q], 4);
        pel[q] += __shfl_xor_sync(0xFFFFFFFFu, pel[q], 8);
        pel[q] += __shfl_xor_sync(0xFFFFFFFFu, pel[q], 16);
        per_[q] += __shfl_xor_sync(0xFFFFFFFFu, per_[q], 4);
        per_[q] += __shfl_xor_sync(0xFFFFFFFFu, per_[q], 8);
        per_[q] += __shfl_xor_sync(0xFFFFFFFFu, per_[q], 16);
    }
    __syncthreads();
    if (g == 0){
        #pragma unroll
        for (int nt = 0; nt < 4; nt++)
            #pragma unroll
            for (int par = 0; par < 2; par++){
                int iloc = warp_n*32 + nt*8 + 2*t + par;
                rel[warp_m*128 + iloc] = pel[nt*2+par];
                rer[warp_m*128 + iloc] = per_[nt*2+par];
            }
    }
    __syncthreads();
    if (tid < 128){
        float se = rel[tid] + rel[128 + tid];
        float sr = rer[tid] + rer[128 + tid];
        int gi = b*NN + i0 + tid;
        g_eel [gi] = __expf(se);
        g_eel2[gi] = __expf(0.2f*se);
        g_eer [gi] = __expf(sr);
        g_eer2[gi] = __expf(0.2f*sr);
    }
}

// ---------------- FUSED scores+PV (R14 core + split commit groups) ----------------
#define SPV_JH  0
#define SPV_JL  TILEB1
#define SPV_EIH (2*TILEB1)
#define SPV_EIL (SPV_EIH + 8704)
#define SPV_ZH  (SPV_EIL + 8704)
#define SPV_ZL  (SPV_ZH + 10240)
#define SPV_ELI (SPV_ZL + 10240)
#define SPV_ELI2 (SPV_ELI + 2048)
#define SPV_RED SPV_EIH
#define SMEM_SPV (SPV_ELI2 + 2048)

__global__ void __launch_bounds__(256,2) k_spv(const float* __restrict__ bias){
    extern __shared__ char smem[];
    uint32_t sb = sm32(smem);
    float* sEli  = (float*)(smem + SPV_ELI);
    float* sEli2 = (float*)(smem + SPV_ELI2);
    float* red   = (float*)(smem + SPV_RED);

    int tid = threadIdx.x;
    int w = tid >> 5, lane = tid & 31;
    int g = lane >> 2, t = lane & 3;
    int jt = blockIdx.x, b = blockIdx.y;
    int j0 = jt * 128;

    #pragma unroll
    for (int p = 0; p < 2; p++){
        sEli [tid + 256*p] = g_eel [b*NN + tid + 256*p];
        sEli2[tid + 256*p] = g_eel2[b*NN + tid + 256*p];
    }

    int jg0 = j0 + w*16 + g;
    float Er0  = g_eer [b*NN + jg0],     Er1  = g_eer [b*NN + jg0 + 8];
    float Er20 = g_eer2[b*NN + jg0],     Er21 = g_eer2[b*NN + jg0 + 8];
    float th = g_th[b];

    uint32_t aoffJ  = ((w*16 + (lane & 15))*PITCH + (lane >> 4)*8)*2;
    uint32_t boffE4 = (((lane & 7) + ((lane >> 4) << 3))*PITCH  + ((lane >> 3) & 1)*8)*2;
    uint32_t boffZ4 = (((lane & 7) + ((lane >> 4) << 3))*PITCH2 + ((lane >> 3) & 1)*8)*2;

    const __nv_bfloat16* Ehb = g_Ehi + (size_t)b*NN*DD;
    const __nv_bfloat16* Elb = g_Elo + (size_t)b*NN*DD;
    const __nv_bfloat16* zh  = g_zThi + (size_t)b*DD*NN;
    const __nv_bfloat16* zl  = g_zTlo + (size_t)b*DD*NN;

    LDTILE(SPV_JH, Ehb + (size_t)j0*DD);
    LDTILE(SPV_JL, Elb + (size_t)j0*DD);

    // split commit groups: E first (older), Z second (newer)
    #define ISSUE_E(icv) do { \
        const __nv_bfloat16* _eh = Ehb + (size_t)((icv)*32)*DD; \
        const __nv_bfloat16* _el = Elb + (size_t)((icv)*32)*DD; \
        _Pragma("unroll") \
        for (int _p = 0; _p < 2; _p++){ \
            int _cid = tid + 256*_p; \
            int _row = _cid >> 4, _kc = _cid & 15; \
            cp16(sb + SPV_EIH + (_row*PITCH + _kc*8)*2, _eh + (size_t)_row*DD + _kc*8); \
            cp16(sb + SPV_EIL + (_row*PITCH + _kc*8)*2, _el + (size_t)_row*DD + _kc*8); \
        } \
        cp_commit(); \
    } while(0)
    #define ISSUE_Z(icv) do { \
        _Pragma("unroll") \
        for (int _p = 0; _p < 2; _p++){ \
            int _cid = tid + 256*_p; \
            int _row = _cid >> 2, _seg = _cid & 3; \
            cp16(sb + SPV_ZH + (_row*PITCH2 + _seg*8)*2, zh + (size_t)_row*NN + (icv)*32 + _seg*8); \
            cp16(sb + SPV_ZL + (_row*PITCH2 + _seg*8)*2, zl + (size_t)_row*NN + (icv)*32 + _seg*8); \
        } \
        cp_commit(); \
    } while(0)

    ISSUE_E(0);
    ISSUE_Z(0);

    float hacc[16][4];
    #pragma unroll
    for (int q = 0; q < 16; q++)
        #pragma unroll
        for (int c = 0; c < 4; c++) hacc[q][c] = 0.f;
    float cs0 = 0.f, cs1 = 0.f;

    #pragma unroll 1
    for (int ic = 0; ic < 16; ic++){
        cp_wait1();              // E tiles of this chunk ready (Z may still fly)
        __syncthreads();

        // ---- S = Ehj*Ehi + Ehj*Eli + Elj*Ehi  (shared A-frags, x4 B-loads)
        float s[4][4];
        #pragma unroll
        for (int nt = 0; nt < 4; nt++)
            #pragma unroll
            for (int c = 0; c < 4; c++) s[nt][c] = 0.f;

        #pragma unroll 2
        for (int ks = 0; ks < 8; ks++){
            uint32_t aH[4], aL[4];
            ldmA(aH, sb + SPV_JH + aoffJ + ks*32);
            ldmA(aL, sb + SPV_JL + aoffJ + ks*32);
            uint32_t bH0[4], bH1[4], bL0[4], bL1[4];
            ldmB4(bH0, sb + SPV_EIH + boffE4 + ks*32);
            ldmB4(bH1, sb + SPV_EIH + boffE4 + 16*PITCH*2 + ks*32);
            ldmB4(bL0, sb + SPV_EIL + boffE4 + ks*32);
            ldmB4(bL1, sb + SPV_EIL + boffE4 + 16*PITCH*2 + ks*32);
            mma16816(s[0], aH, &bH0[0]); mma16816(s[1], aH, &bH0[2]);
            mma16816(s[2], aH, &bH1[0]); mma16816(s[3], aH, &bH1[2]);
            mma16816(s[0], aH, &bL0[0]); mma16816(s[1], aH, &bL0[2]);
            mma16816(s[2], aH, &bL1[0]); mma16816(s[3], aH, &bL1[2]);
            mma16816(s[0], aL, &bH0[0]); mma16816(s[1], aL, &bH0[2]);
            mma16816(s[2], aL, &bH1[0]); mma16816(s[3], aL, &bH1[2]);
        }

        // ---- mask/exp -> P in regs; cs accumulate (overlaps Z arrival)
        int ibase = ic*32;
        #pragma unroll
        for (int nt = 0; nt < 4; nt++){
            #pragma unroll
            for (int c = 0; c < 4; c++){
                int ig = ibase + nt*8 + 2*t + (c & 1);
                int jg = jg0 + 8*(c >> 1);
                float sv = s[nt][c];
                float p = 0.f;
                if (sv > th || ig == jg){
                    float q = sEli[ig] * ((c >> 1) ? Er1 : Er0);
                    p = (q > 1.f) ? q : sEli2[ig] * ((c >> 1) ? Er21 : Er20);
                }
                if (c >> 1) cs1 += p; else cs0 += p;
                s[nt][c] = p;
            }
        }
        uint32_t pf[2][4];
        #pragma unroll
        for (int kt = 0; kt < 2; kt++){
            pf[kt][0] = packbf(s[2*kt][0],   s[2*kt][1]);
            pf[kt][1] = packbf(s[2*kt][2],   s[2*kt][3]);
            pf[kt][2] = packbf(s[2*kt+1][0], s[2*kt+1][1]);
            pf[kt][3] = packbf(s[2*kt+1][2], s[2*kt+1][3]);
        }

        cp_wait0();              // Z tiles ready
        __syncthreads();

        // ---- PV: h += P * (zh + zl)
        #pragma unroll
        for (int kt = 0; kt < 2; kt++){
            #pragma unroll
            for (int ntp = 0; ntp < 8; ntp++){
                uint32_t bh[4], bl[4];
                ldmB4(bh, sb + SPV_ZH + boffZ4 + ntp*(16*PITCH2*2) + kt*32);
                ldmB4(bl, sb + SPV_ZL + boffZ4 + ntp*(16*PITCH2*2) + kt*32);
                mma16816(hacc[2*ntp],   pf[kt], &bh[0]);
                mma16816(hacc[2*ntp+1], pf[kt], &bh[2]);
                mma16816(hacc[2*ntp],   pf[kt], &bl[0]);
                mma16816(hacc[2*ntp+1], pf[kt], &bl[2]);
            }
        }

        __syncthreads();
        if (ic + 1 < 16){ ISSUE_E(ic+1); ISSUE_Z(ic+1); }
    }
    #undef ISSUE_E
    #undef ISSUE_Z

    // ---- final: cs reduce, /cs, +bias, elu, pool over j
    cs0 += __shfl_xor_sync(0xFFFFFFFFu, cs0, 1);
    cs0 += __shfl_xor_sync(0xFFFFFFFFu, cs0, 2);
    cs1 += __shfl_xor_sync(0xFFFFFFFFu, cs1, 1);
    cs1 += __shfl_xor_sync(0xFFFFFFFFu, cs1, 2);
    float inv0 = 1.f / cs0, inv1 = 1.f / cs1;

    #pragma unroll
    for (int ntd = 0; ntd < 16; ntd++){
        float pd0, pd1;
        {
            float v0 = hacc[ntd][0]*inv0 + bias[ntd*8 + 2*t];
            float v1 = hacc[ntd][1]*inv0 + bias[ntd*8 + 2*t + 1];
            float v2 = hacc[ntd][2]*inv1 + bias[ntd*8 + 2*t];
            float v3 = hacc[ntd][3]*inv1 + bias[ntd*8 + 2*t + 1];
            v0 = v0 > 0.f ? v0 : expm1f(v0);
            v1 = v1 > 0.f ? v1 : expm1f(v1);
            v2 = v2 > 0.f ? v2 : expm1f(v2);
            v3 = v3 > 0.f ? v3 : expm1f(v3);
            pd0 = v0 + v2; pd1 = v1 + v3;
        }
        pd0 += __shfl_xor_sync(0xFFFFFFFFu, pd0, 4);
        pd0 += __shfl_xor_sync(0xFFFFFFFFu, pd0, 8);
        pd0 += __shfl_xor_sync(0xFFFFFFFFu, pd0, 16);
        pd1 += __shfl_xor_sync(0xFFFFFFFFu, pd1, 4);
        pd1 += __shfl_xor_sync(0xFFFFFFFFu, pd1, 8);
        pd1 += __shfl_xor_sync(0xFFFFFFFFu, pd1, 16);
        if (g == 0){
            red[w*128 + ntd*8 + 2*t]     = pd0;
            red[w*128 + ntd*8 + 2*t + 1] = pd1;
        }
    }
    __syncthreads();
    if (tid < 128){
        float tt = 0.f;
        #pragma unroll
        for (int x = 0; x < 8; x++) tt += red[x*128 + tid];
        g_pool[(b*4 + jt)*DD + tid] = tt;
    }
}

// ---------------- final: mean over nodes ----------------
__global__ void k_out(float* __restrict__ out){
    int b = blockIdx.x, d = threadIdx.x;
    float s = g_pool[(b*4+0)*DD + d] + g_pool[(b*4+1)*DD + d]
            + g_pool[(b*4+2)*DD + d] + g_pool[(b*4+3)*DD + d];
    out[b*DD + d] = s * (1.f / (float)NN);
}

extern "C" void kernel_launch(void* const* d_in, const int* in_sizes, int n_in,
                              void* d_out, int out_size){
    const float* E    = (const float*)d_in[0];
    const float* W    = (const float*)d_in[1];
    const float* al   = (const float*)d_in[2];
    const float* ar   = (const float*)d_in[3];
    const float* bias = (const float*)d_in[4];
    float* out = (float*)d_out;

    cudaFuncSetAttribute(k_z_mma, cudaFuncAttributeMaxDynamicSharedMemorySize, SMEM_Z);
    cudaFuncSetAttribute(k_spv,   cudaFuncAttributeMaxDynamicSharedMemorySize, SMEM_SPV);

    k_split <<<dim3(8,64), 256>>>(E);
    k_Wt    <<<dim3(4,4), dim3(32,8)>>>(W);
    k_thresh<<<64, 128>>>();
    k_z_mma <<<dim3(4,64), 256, SMEM_Z>>>(al, ar);
    k_spv   <<<dim3(4,64), 256, SMEM_SPV>>>(bias);
    k_out   <<<64, 128>>>(out);
}

// round 17
// speedup vs baseline: 1.0617x; 1.0577x over previous
#include <cuda_runtime.h>
#include <cuda_bf16.h>
#include <math.h>
#include <stdint.h>

#define BB 64
#define NN 512
#define DD 128
#define PITCH 136   // bf16 elems per smem row (272B): conflict-free ldmatrix
#define PITCH2 40   // bf16 elems per smem row for 32-wide k-chunks (80B)

typedef unsigned long long ull;

__device__ __forceinline__ unsigned sm32(const void* p){
    return (unsigned)__cvta_generic_to_shared(p);
}
__device__ __forceinline__ void cp16(unsigned dst, const void* src){
    asm volatile("cp.async.cg.shared.global [%0], [%1], 16;" :: "r"(dst), "l"(src));
}
__device__ __forceinline__ void cp_commit(){ asm volatile("cp.async.commit_group;"); }
__device__ __forceinline__ void cp_wait0(){ asm volatile("cp.async.wait_group 0;" ::: "memory"); }
__device__ __forceinline__ void cp_wait1(){ asm volatile("cp.async.wait_group 1;" ::: "memory"); }

// ---- warp-level MMA primitives ----
__device__ __forceinline__ void ldmA(uint32_t* a, uint32_t addr){
    asm volatile("ldmatrix.sync.aligned.m8n8.x4.shared.b16 {%0,%1,%2,%3}, [%4];"
        : "=r"(a[0]), "=r"(a[1]), "=r"(a[2]), "=r"(a[3]) : "r"(addr));
}
__device__ __forceinline__ void ldmB4(uint32_t* b, uint32_t addr){
    asm volatile("ldmatrix.sync.aligned.m8n8.x4.shared.b16 {%0,%1,%2,%3}, [%4];"
        : "=r"(b[0]), "=r"(b[1]), "=r"(b[2]), "=r"(b[3]) : "r"(addr));
}
__device__ __forceinline__ void ldmB(uint32_t* b, uint32_t addr){
    asm volatile("ldmatrix.sync.aligned.m8n8.x2.shared.b16 {%0,%1}, [%2];"
        : "=r"(b[0]), "=r"(b[1]) : "r"(addr));
}
__device__ __forceinline__ void mma16816(float* d, const uint32_t* a, const uint32_t* b){
    asm volatile("mma.sync.aligned.m16n8k16.row.col.f32.bf16.bf16.f32 "
        "{%0,%1,%2,%3}, {%4,%5,%6,%7}, {%8,%9}, {%0,%1,%2,%3};"
        : "+f"(d[0]), "+f"(d[1]), "+f"(d[2]), "+f"(d[3])
        : "r"(a[0]), "r"(a[1]), "r"(a[2]), "r"(a[3]), "r"(b[0]), "r"(b[1]));
}
__device__ __forceinline__ uint32_t packbf(float lo, float hi){
    __nv_bfloat162 v = __halves2bfloat162(__float2bfloat16(lo), __float2bfloat16(hi));
    return *(uint32_t*)&v;
}

// Scratch (static device globals; no allocation)
__device__ __nv_bfloat16 g_Ehi[(size_t)BB*NN*DD];
__device__ __nv_bfloat16 g_Elo[(size_t)BB*NN*DD];
__device__ __nv_bfloat16 g_Wthi[DD*DD];
__device__ __nv_bfloat16 g_Wtlo[DD*DD];
__device__ __nv_bfloat16 g_zThi[(size_t)BB*DD*NN];
__device__ __nv_bfloat16 g_zTlo[(size_t)BB*DD*NN];
__device__ float g_psum[BB*8*DD];
__device__ float g_eel [BB*NN];
__device__ float g_eel2[BB*NN];
__device__ float g_eer [BB*NN];
__device__ float g_eer2[BB*NN];
__device__ float g_th[BB];
__device__ float g_pool[BB*4*DD];

// ---------------- E split + psum; blockIdx.y == BB rows do W^T split ----------------
__global__ void k_split(const float* __restrict__ E, const float* __restrict__ W){
    __shared__ float sm[32*33];
    int tid = threadIdx.x;

    if (blockIdx.y == BB){
        // W -> W^T bf16 hi/lo: 2 tiles of 32x32 per CTA (blockIdx.x in 0..7)
        float (*t)[33] = (float(*)[33])sm;
        int tx = tid & 31, ty = tid >> 5;   // 32 x 8
        #pragma unroll 1
        for (int q = 0; q < 2; q++){
            int tt = blockIdx.x*2 + q;
            int k0 = (tt & 3)*32, d0 = (tt >> 2)*32;
            __syncthreads();
            #pragma unroll
            for (int yy = 0; yy < 32; yy += 8)
                t[ty+yy][tx] = W[(size_t)(k0+ty+yy)*DD + d0 + tx];
            __syncthreads();
            #pragma unroll
            for (int yy = 0; yy < 32; yy += 8){
                float v = t[tx][ty+yy];
                size_t idx = (size_t)(d0+ty+yy)*DD + k0 + tx;
                __nv_bfloat16 h = __float2bfloat16(v);
                g_Wthi[idx] = h;
                g_Wtlo[idx] = __float2bfloat16(v - __bfloat162float(h));
            }
        }
        return;
    }

    float4 (*red)[32] = (float4(*)[32])sm;
    int b = blockIdx.y, rc = blockIdx.x;
    int r = tid >> 5, d4 = tid & 31;
    const float* Eb = E + (size_t)b*NN*DD + (size_t)rc*64*DD;
    __nv_bfloat16* Eh = g_Ehi + (size_t)b*NN*DD + (size_t)rc*64*DD;
    __nv_bfloat16* El = g_Elo + (size_t)b*NN*DD + (size_t)rc*64*DD;
    float4 ps = make_float4(0.f,0.f,0.f,0.f);
    #pragma unroll
    for (int q = 0; q < 8; q++){
        size_t off = (size_t)(r + q*8)*DD + d4*4;
        float4 v = *(const float4*)(Eb + off);
        __nv_bfloat16 h0 = __float2bfloat16(v.x), h1 = __float2bfloat16(v.y);
        __nv_bfloat16 h2 = __float2bfloat16(v.z), h3 = __float2bfloat16(v.w);
        *(__nv_bfloat162*)&Eh[off]   = __halves2bfloat162(h0, h1);
        *(__nv_bfloat162*)&Eh[off+2] = __halves2bfloat162(h2, h3);
        *(__nv_bfloat162*)&El[off]   = __halves2bfloat162(
            __float2bfloat16(v.x - __bfloat162float(h0)), __float2bfloat16(v.y - __bfloat162float(h1)));
        *(__nv_bfloat162*)&El[off+2] = __halves2bfloat162(
            __float2bfloat16(v.z - __bfloat162float(h2)), __float2bfloat16(v.w - __bfloat162float(h3)));
        ps.x += v.x; ps.y += v.y; ps.z += v.z; ps.w += v.w;
    }
    red[r][d4] = ps;
    __syncthreads();
    if (r == 0){
        float4 s = red[0][d4];
        #pragma unroll
        for (int q = 1; q < 8; q++){
            s.x += red[q][d4].x; s.y += red[q][d4].y;
            s.z += red[q][d4].z; s.w += red[q][d4].w;
        }
        *(float4*)&g_psum[(b*8 + rc)*DD + d4*4] = s;
    }
}

#define TILEB1 (128*PITCH*2)            // 34816

#define LDTILE(dstoff, Src) do { \
    _Pragma("unroll") \
    for (int _p = 0; _p < 8; _p++){ \
        int _cid = tid + 256*_p; \
        int _row = _cid >> 4, _kc = _cid & 15; \
        cp16(sb + (dstoff) + (_row*PITCH + _kc*8)*2, (Src) + (size_t)_row*DD + _kc*8); \
    } \
} while(0)

#define TERM(at, bt) do { \
    _Pragma("unroll 2") \
    for (int ks = 0; ks < 8; ks++){ \
        uint32_t af[4][4], bf[4][2]; \
        _Pragma("unroll") \
        for (int mt = 0; mt < 4; mt++) ldmA(af[mt], sb + (at) + aoff[mt] + ks*32); \
        _Pragma("unroll") \
        for (int nt = 0; nt < 4; nt++) ldmB(bf[nt], sb + (bt) + boff[nt] + ks*32); \
        _Pragma("unroll") \
        for (int mt = 0; mt < 4; mt++) \
            _Pragma("unroll") \
            for (int nt = 0; nt < 4; nt++) \
                mma16816(d[mt][nt], af[mt], bf[nt]); \
    } \
} while(0)

// ---------------- HMMA z^T + fused thresh + coalesced store staging ----------------
#define SMS_T0 0
#define SMS_T1 TILEB1
#define SMS_T2 (2*TILEB1)
#define SMZ_RED (3*TILEB1)
#define SMEM_Z  (SMZ_RED + 4096)

__global__ void __launch_bounds__(256,2) k_z_mma(const float* __restrict__ attn_l,
                                                 const float* __restrict__ attn_r){
    extern __shared__ char smem[];
    uint32_t sb = sm32(smem);
    float* rel = (float*)(smem + SMZ_RED);
    float* rer = rel + 256;

    int tid = threadIdx.x;
    int wid = tid >> 5, lane = tid & 31;
    int warp_m = wid >> 2, warp_n = wid & 3;
    int g = lane >> 2, t = lane & 3;
    int it = blockIdx.x, b = blockIdx.y;
    int i0 = it * 128;

    uint32_t aoff[4], boff[4];
    #pragma unroll
    for (int mt = 0; mt < 4; mt++)
        aoff[mt] = ((warp_m*64 + mt*16 + (lane & 15))*PITCH + (lane >> 4)*8)*2;
    #pragma unroll
    for (int nt = 0; nt < 4; nt++)
        boff[nt] = ((warp_n*32 + nt*8 + (lane & 7))*PITCH + ((lane >> 3) & 1)*8)*2;

    float d[4][4][4];
    #pragma unroll
    for (int mt = 0; mt < 4; mt++)
        #pragma unroll
        for (int nt = 0; nt < 4; nt++)
            #pragma unroll
            for (int c = 0; c < 4; c++) d[mt][nt][c] = 0.f;

    const __nv_bfloat16* Eh = g_Ehi + (size_t)b*NN*DD + (size_t)i0*DD;
    const __nv_bfloat16* El = g_Elo + (size_t)b*NN*DD + (size_t)i0*DD;

    float al8[8], ar8[8];
    #pragma unroll
    for (int mt = 0; mt < 4; mt++)
        #pragma unroll
        for (int half = 0; half < 2; half++){
            int dloc = warp_m*64 + mt*16 + g + 8*half;
            al8[mt*2+half] = attn_l[dloc];
            ar8[mt*2+half] = attn_r[dloc];
        }

    LDTILE(SMS_T0, g_Wthi);
    LDTILE(SMS_T1, El);
    cp_commit();
    LDTILE(SMS_T2, Eh);
    cp_commit();

    // fused thresh (it==0 CTA per batch) — overlaps the cp.async loads
    if (it == 0){
        if (tid < 128){
            float s = 0.f;
            #pragma unroll
            for (int q = 0; q < 8; q++) s += g_psum[(b*8 + q)*DD + tid];
            rel[tid] = s * s;
        }
        __syncthreads();
        for (int o = 64; o > 0; o >>= 1){
            if (tid < o) rel[tid] += rel[tid+o];
            __syncthreads();
        }
        if (tid == 0) g_th[b] = rel[0] * (1.f / ((float)NN * (float)NN));
    }

    cp_wait1();
    __syncthreads();
    TERM(SMS_T0, SMS_T1);            // Wth * El
    __syncthreads();
    LDTILE(SMS_T1, g_Wtlo);
    cp_commit();
    cp_wait1();
    __syncthreads();
    TERM(SMS_T0, SMS_T2);            // Wth * Eh
    cp_wait0();
    __syncthreads();
    TERM(SMS_T1, SMS_T2);            // Wtl * Eh
    __syncthreads();                 // all warps done reading tiles — free for staging

    // stage zT hi/lo in smem (conflict-free), compute el/er partials
    __nv_bfloat16* zbh = (__nv_bfloat16*)(smem + SMS_T0);   // [128][PITCH]
    __nv_bfloat16* zbl = (__nv_bfloat16*)(smem + SMS_T1);
    float pel[8], per_[8];
    #pragma unroll
    for (int q = 0; q < 8; q++){ pel[q] = 0.f; per_[q] = 0.f; }
    #pragma unroll
    for (int mt = 0; mt < 4; mt++){
        #pragma unroll
        for (int half = 0; half < 2; half++){
            int dloc = warp_m*64 + mt*16 + g + 8*half;
            float wl = al8[mt*2+half], wr = ar8[mt*2+half];
            #pragma unroll
            for (int nt = 0; nt < 4; nt++){
                float v0 = d[mt][nt][half*2 + 0];
                float v1 = d[mt][nt][half*2 + 1];
                pel[nt*2+0] += wl*v0; pel[nt*2+1] += wl*v1;
                per_[nt*2+0] += wr*v0; per_[nt*2+1] += wr*v1;
                __nv_bfloat16 h0 = __float2bfloat16(v0);
                __nv_bfloat16 h1 = __float2bfloat16(v1);
                __nv_bfloat16 l0 = __float2bfloat16(v0 - __bfloat162float(h0));
                __nv_bfloat16 l1 = __float2bfloat16(v1 - __bfloat162float(h1));
                int ii = warp_n*32 + nt*8 + 2*t;
                *(__nv_bfloat162*)&zbh[dloc*PITCH + ii] = __halves2bfloat162(h0, h1);
                *(__nv_bfloat162*)&zbl[dloc*PITCH + ii] = __halves2bfloat162(l0, l1);
            }
        }
    }
    __syncthreads();
    // coalesced copy-out: 16B per thread, 16 rows per pass
    {
        __nv_bfloat16* zhg = g_zThi + (size_t)b*DD*NN + i0;
        __nv_bfloat16* zlg = g_zTlo + (size_t)b*DD*NN + i0;
        int row = tid >> 4, kc = tid & 15;
        #pragma unroll
        for (int pass = 0; pass < 8; pass++){
            int rr = pass*16 + row;
            float4 vh = *(float4*)&zbh[rr*PITCH + kc*8];
            float4 vl = *(float4*)&zbl[rr*PITCH + kc*8];
            *(float4*)&zhg[(size_t)rr*NN + kc*8] = vh;
            *(float4*)&zlg[(size_t)rr*NN + kc*8] = vl;
        }
    }

    // el/er reduction + exp tables
    #pragma unroll
    for (int q = 0; q < 8; q++){
        pel[q] += __shfl_xor_sync(0xFFFFFFFFu, pel[q], 4);
        pel[q] += __shfl_xor_sync(0xFFFFFFFFu, pel[q], 8);
        pel[q] += __shfl_xor_sync(0xFFFFFFFFu, pel[q], 16);
        per_[q] += __shfl_xor_sync(0xFFFFFFFFu, per_[q], 4);
        per_[q] += __shfl_xor_sync(0xFFFFFFFFu, per_[q], 8);
        per_[q] += __shfl_xor_sync(0xFFFFFFFFu, per_[q], 16);
    }
    __syncthreads();
    if (g == 0){
        #pragma unroll
        for (int nt = 0; nt < 4; nt++)
            #pragma unroll
            for (int par = 0; par < 2; par++){
                int iloc = warp_n*32 + nt*8 + 2*t + par;
                rel[warp_m*128 + iloc] = pel[nt*2+par];
                rer[warp_m*128 + iloc] = per_[nt*2+par];
            }
    }
    __syncthreads();
    if (tid < 128){
        float se = rel[tid] + rel[128 + tid];
        float sr = rer[tid] + rer[128 + tid];
        int gi = b*NN + i0 + tid;
        g_eel [gi] = __expf(se);
        g_eel2[gi] = __expf(0.2f*se);
        g_eer [gi] = __expf(sr);
        g_eer2[gi] = __expf(0.2f*sr);
    }
}

// ---------------- FUSED scores+PV (R14-exact) ----------------
#define SPV_JH  0
#define SPV_JL  TILEB1
#define SPV_EIH (2*TILEB1)
#define SPV_EIL (SPV_EIH + 8704)
#define SPV_ZH  (SPV_EIL + 8704)
#define SPV_ZL  (SPV_ZH + 10240)
#define SPV_ELI (SPV_ZL + 10240)
#define SPV_ELI2 (SPV_ELI + 2048)
#define SPV_RED SPV_EIH
#define SMEM_SPV (SPV_ELI2 + 2048)

__global__ void __launch_bounds__(256,2) k_spv(const float* __restrict__ bias){
    extern __shared__ char smem[];
    uint32_t sb = sm32(smem);
    float* sEli  = (float*)(smem + SPV_ELI);
    float* sEli2 = (float*)(smem + SPV_ELI2);
    float* red   = (float*)(smem + SPV_RED);

    int tid = threadIdx.x;
    int w = tid >> 5, lane = tid & 31;
    int g = lane >> 2, t = lane & 3;
    int jt = blockIdx.x, b = blockIdx.y;
    int j0 = jt * 128;

    #pragma unroll
    for (int p = 0; p < 2; p++){
        sEli [tid + 256*p] = g_eel [b*NN + tid + 256*p];
        sEli2[tid + 256*p] = g_eel2[b*NN + tid + 256*p];
    }

    int jg0 = j0 + w*16 + g;
    float Er0  = g_eer [b*NN + jg0],     Er1  = g_eer [b*NN + jg0 + 8];
    float Er20 = g_eer2[b*NN + jg0],     Er21 = g_eer2[b*NN + jg0 + 8];
    float th = g_th[b];

    uint32_t aoffJ  = ((w*16 + (lane & 15))*PITCH + (lane >> 4)*8)*2;
    uint32_t boffE4 = (((lane & 7) + ((lane >> 4) << 3))*PITCH  + ((lane >> 3) & 1)*8)*2;
    uint32_t boffZ4 = (((lane & 7) + ((lane >> 4) << 3))*PITCH2 + ((lane >> 3) & 1)*8)*2;

    const __nv_bfloat16* Ehb = g_Ehi + (size_t)b*NN*DD;
    const __nv_bfloat16* Elb = g_Elo + (size_t)b*NN*DD;
    const __nv_bfloat16* zh  = g_zThi + (size_t)b*DD*NN;
    const __nv_bfloat16* zl  = g_zTlo + (size_t)b*DD*NN;

    LDTILE(SPV_JH, Ehb + (size_t)j0*DD);
    LDTILE(SPV_JL, Elb + (size_t)j0*DD);

    #define ISSUE_CHUNK(icv) do { \
        const __nv_bfloat16* _eh = Ehb + (size_t)((icv)*32)*DD; \
        const __nv_bfloat16* _el = Elb + (size_t)((icv)*32)*DD; \
        _Pragma("unroll") \
        for (int _p = 0; _p < 2; _p++){ \
            int _cid = tid + 256*_p; \
            int _row = _cid >> 4, _kc = _cid & 15; \
            cp16(sb + SPV_EIH + (_row*PITCH + _kc*8)*2, _eh + (size_t)_row*DD + _kc*8); \
            cp16(sb + SPV_EIL + (_row*PITCH + _kc*8)*2, _el + (size_t)_row*DD + _kc*8); \
        } \
        _Pragma("unroll") \
        for (int _p = 0; _p < 2; _p++){ \
            int _cid = tid + 256*_p; \
            int _row = _cid >> 2, _seg = _cid & 3; \
            cp16(sb + SPV_ZH + (_row*PITCH2 + _seg*8)*2, zh + (size_t)_row*NN + (icv)*32 + _seg*8); \
            cp16(sb + SPV_ZL + (_row*PITCH2 + _seg*8)*2, zl + (size_t)_row*NN + (icv)*32 + _seg*8); \
        } \
        cp_commit(); \
    } while(0)

    ISSUE_CHUNK(0);

    float hacc[16][4];
    #pragma unroll
    for (int q = 0; q < 16; q++)
        #pragma unroll
        for (int c = 0; c < 4; c++) hacc[q][c] = 0.f;
    float cs0 = 0.f, cs1 = 0.f;

    #pragma unroll 1
    for (int ic = 0; ic < 16; ic++){
        cp_wait0();
        __syncthreads();

        float s[4][4];
        #pragma unroll
        for (int nt = 0; nt < 4; nt++)
            #pragma unroll
            for (int c = 0; c < 4; c++) s[nt][c] = 0.f;

        #pragma unroll 2
        for (int ks = 0; ks < 8; ks++){
            uint32_t aH[4], aL[4];
            ldmA(aH, sb + SPV_JH + aoffJ + ks*32);
            ldmA(aL, sb + SPV_JL + aoffJ + ks*32);
            uint32_t bH0[4], bH1[4], bL0[4], bL1[4];
            ldmB4(bH0, sb + SPV_EIH + boffE4 + ks*32);
            ldmB4(bH1, sb + SPV_EIH + boffE4 + 16*PITCH*2 + ks*32);
            ldmB4(bL0, sb + SPV_EIL + boffE4 + ks*32);
            ldmB4(bL1, sb + SPV_EIL + boffE4 + 16*PITCH*2 + ks*32);
            mma16816(s[0], aH, &bH0[0]); mma16816(s[1], aH, &bH0[2]);
            mma16816(s[2], aH, &bH1[0]); mma16816(s[3], aH, &bH1[2]);
            mma16816(s[0], aH, &bL0[0]); mma16816(s[1], aH, &bL0[2]);
            mma16816(s[2], aH, &bL1[0]); mma16816(s[3], aH, &bL1[2]);
            mma16816(s[0], aL, &bH0[0]); mma16816(s[1], aL, &bH0[2]);
            mma16816(s[2], aL, &bH1[0]); mma16816(s[3], aL, &bH1[2]);
        }

        int ibase = ic*32;
        #pragma unroll
        for (int nt = 0; nt < 4; nt++){
            #pragma unroll
            for (int c = 0; c < 4; c++){
                int ig = ibase + nt*8 + 2*t + (c & 1);
                int jg = jg0 + 8*(c >> 1);
                float sv = s[nt][c];
                float p = 0.f;
                if (sv > th || ig == jg){
                    float q = sEli[ig] * ((c >> 1) ? Er1 : Er0);
                    p = (q > 1.f) ? q : sEli2[ig] * ((c >> 1) ? Er21 : Er20);
                }
                if (c >> 1) cs1 += p; else cs0 += p;
                s[nt][c] = p;
            }
        }

        uint32_t pf[2][4];
        #pragma unroll
        for (int kt = 0; kt < 2; kt++){
            pf[kt][0] = packbf(s[2*kt][0],   s[2*kt][1]);
            pf[kt][1] = packbf(s[2*kt][2],   s[2*kt][3]);
            pf[kt][2] = packbf(s[2*kt+1][0], s[2*kt+1][1]);
            pf[kt][3] = packbf(s[2*kt+1][2], s[2*kt+1][3]);
        }

        #pragma unroll
        for (int kt = 0; kt < 2; kt++){
            #pragma unroll
            for (int ntp = 0; ntp < 8; ntp++){
                uint32_t bh[4], bl[4];
                ldmB4(bh, sb + SPV_ZH + boffZ4 + ntp*(16*PITCH2*2) + kt*32);
                ldmB4(bl, sb + SPV_ZL + boffZ4 + ntp*(16*PITCH2*2) + kt*32);
                mma16816(hacc[2*ntp],   pf[kt], &bh[0]);
                mma16816(hacc[2*ntp+1], pf[kt], &bh[2]);
                mma16816(hacc[2*ntp],   pf[kt], &bl[0]);
                mma16816(hacc[2*ntp+1], pf[kt], &bl[2]);
            }
        }

        __syncthreads();
        if (ic + 1 < 16) ISSUE_CHUNK(ic+1);
    }
    #undef ISSUE_CHUNK

    cs0 += __shfl_xor_sync(0xFFFFFFFFu, cs0, 1);
    cs0 += __shfl_xor_sync(0xFFFFFFFFu, cs0, 2);
    cs1 += __shfl_xor_sync(0xFFFFFFFFu, cs1, 1);
    cs1 += __shfl_xor_sync(0xFFFFFFFFu, cs1, 2);
    float inv0 = 1.f / cs0, inv1 = 1.f / cs1;

    #pragma unroll
    for (int ntd = 0; ntd < 16; ntd++){
        float pd0, pd1;
        {
            float v0 = hacc[ntd][0]*inv0 + bias[ntd*8 + 2*t];
            float v1 = hacc[ntd][1]*inv0 + bias[ntd*8 + 2*t + 1];
            float v2 = hacc[ntd][2]*inv1 + bias[ntd*8 + 2*t];
            float v3 = hacc[ntd][3]*inv1 + bias[ntd*8 + 2*t + 1];
            v0 = v0 > 0.f ? v0 : expm1f(v0);
            v1 = v1 > 0.f ? v1 : expm1f(v1);
            v2 = v2 > 0.f ? v2 : expm1f(v2);
            v3 = v3 > 0.f ? v3 : expm1f(v3);
            pd0 = v0 + v2; pd1 = v1 + v3;
        }
        pd0 += __shfl_xor_sync(0xFFFFFFFFu, pd0, 4);
        pd0 += __shfl_xor_sync(0xFFFFFFFFu, pd0, 8);
        pd0 += __shfl_xor_sync(0xFFFFFFFFu, pd0, 16);
        pd1 += __shfl_xor_sync(0xFFFFFFFFu, pd1, 4);
        pd1 += __shfl_xor_sync(0xFFFFFFFFu, pd1, 8);
        pd1 += __shfl_xor_sync(0xFFFFFFFFu, pd1, 16);
        if (g == 0){
            red[w*128 + ntd*8 + 2*t]     = pd0;
            red[w*128 + ntd*8 + 2*t + 1] = pd1;
        }
    }
    __syncthreads();
    if (tid < 128){
        float tt = 0.f;
        #pragma unroll
        for (int x = 0; x < 8; x++) tt += red[x*128 + tid];
        g_pool[(b*4 + jt)*DD + tid] = tt;
    }
}

// ---------------- final: mean over nodes ----------------
__global__ void k_out(float* __restrict__ out){
    int b = blockIdx.x, d = threadIdx.x;
    float s = g_pool[(b*4+0)*DD + d] + g_pool[(b*4+1)*DD + d]
            + g_pool[(b*4+2)*DD + d] + g_pool[(b*4+3)*DD + d];
    out[b*DD + d] = s * (1.f / (float)NN);
}

extern "C" void kernel_launch(void* const* d_in, const int* in_sizes, int n_in,
                              void* d_out, int out_size){
    const float* E    = (const float*)d_in[0];
    const float* W    = (const float*)d_in[1];
    const float* al   = (const float*)d_in[2];
    const float* ar   = (const float*)d_in[3];
    const float* bias = (const float*)d_in[4];
    float* out = (float*)d_out;

    cudaFuncSetAttribute(k_z_mma, cudaFuncAttributeMaxDynamicSharedMemorySize, SMEM_Z);
    cudaFuncSetAttribute(k_spv,   cudaFuncAttributeMaxDynamicSharedMemorySize, SMEM_SPV);

    k_split <<<dim3(8,65), 256>>>(E, W);
    k_z_mma <<<dim3(4,64), 256, SMEM_Z>>>(al, ar);
    k_spv   <<<dim3(4,64), 256, SMEM_SPV>>>(bias);
    k_out   <<<64, 128>>>(out);
}